// round 12
// baseline (speedup 1.0000x reference)
#include <cuda_runtime.h>
#include <cuda_bf16.h>
#include <cstdint>

#define Bv 2
#define Sv 2048
#define Dv 1024
#define Hv 16
#define DHv 64
#define NTv (Bv*Sv)

// Scratch (static device globals; allocation-free at launch time)
__device__ float g_o[(size_t)NTv*Dv];         // attn@V in [b,s,D] layout
__device__ int   g_mall;                      // 1 if mask is all-nonzero
// bf16 hi/lo planes produced by the QKV GEMM epilogue
__device__ __nv_bfloat16 g_qh[(size_t)Bv*Hv*Sv*DHv];  // [b,h,s,d], pre-scaled 0.125
__device__ __nv_bfloat16 g_ql[(size_t)Bv*Hv*Sv*DHv];
__device__ __nv_bfloat16 g_kh[(size_t)Bv*Hv*Sv*DHv];  // [b,h,s,d]
__device__ __nv_bfloat16 g_kl[(size_t)Bv*Hv*Sv*DHv];
__device__ __nv_bfloat16 g_vth[(size_t)Bv*Hv*Sv*DHv]; // [b,h,d,s] (transposed)
__device__ __nv_bfloat16 g_vtl[(size_t)Bv*Hv*Sv*DHv];

// ===========================================================================
// Helpers
// ===========================================================================
__device__ __forceinline__ uint32_t smem_u32(const void* p) {
    uint32_t a;
    asm("{ .reg .u64 t; cvta.to.shared.u64 t, %1; cvt.u32.u64 %0, t; }"
        : "=r"(a) : "l"(p));
    return a;
}
__device__ __forceinline__ uint32_t swz(uint32_t off) {
    return off ^ ((off >> 3) & 0x70);
}
__device__ __forceinline__ void ldsm4(uint32_t* r, uint32_t addr) {
    asm volatile("ldmatrix.sync.aligned.m8n8.x4.shared.b16 {%0,%1,%2,%3}, [%4];"
                 : "=r"(r[0]), "=r"(r[1]), "=r"(r[2]), "=r"(r[3]) : "r"(addr));
}
__device__ __forceinline__ void mma16816(float* c, const uint32_t* a, const uint32_t* b) {
    asm volatile(
        "mma.sync.aligned.m16n8k16.row.col.f32.bf16.bf16.f32 "
        "{%0,%1,%2,%3}, {%4,%5,%6,%7}, {%8,%9}, {%0,%1,%2,%3};"
        : "+f"(c[0]), "+f"(c[1]), "+f"(c[2]), "+f"(c[3])
        : "r"(a[0]), "r"(a[1]), "r"(a[2]), "r"(a[3]), "r"(b[0]), "r"(b[1]));
}
__device__ __forceinline__ void cvt2(float x, float y, uint32_t& hp, uint32_t& lp) {
    __nv_bfloat16 hx = __float2bfloat16(x);
    __nv_bfloat16 hy = __float2bfloat16(y);
    __nv_bfloat16 lx = __float2bfloat16(x - __bfloat162float(hx));
    __nv_bfloat16 ly = __float2bfloat16(y - __bfloat162float(hy));
    hp = ((uint32_t)__bfloat16_as_ushort(hy) << 16) | __bfloat16_as_ushort(hx);
    lp = ((uint32_t)__bfloat16_as_ushort(ly) << 16) | __bfloat16_as_ushort(lx);
}
// FMA-pipe exp (no MUFU)
__device__ __forceinline__ float fexp(float x) {
    float z  = fmaf(x, 1.4426950408889634f, 12582912.0f);
    int   i  = __float_as_int(z);
    float fi = z - 12582912.0f;
    float f  = fmaf(x, 1.4426950408889634f, -fi);
    float p  = 1.5403530e-4f;
    p = fmaf(p, f, 1.3333558e-3f);
    p = fmaf(p, f, 9.6181291e-3f);
    p = fmaf(p, f, 5.5504109e-2f);
    p = fmaf(p, f, 2.4022651e-1f);
    p = fmaf(p, f, 6.9314718e-1f);
    p = fmaf(p, f, 1.0f);
    return __int_as_float(__float_as_int(p) + (i << 23));
}
#define CP16(dst, src) \
    asm volatile("cp.async.cg.shared.global [%0], [%1], 16;" \
                 :: "r"(dst), "l"(src) : "memory")
#define CP_COMMIT() asm volatile("cp.async.commit_group;" ::: "memory")
#define CP_WAIT(n)  asm volatile("cp.async.wait_group %0;" :: "n"(n) : "memory")

#define TILE_B 16384
#define GEMM_SMEM (4*TILE_B + 1024)

// ===========================================================================
// HMMA bf16x3 GEMM: Y = A @ W^T + bias (unchanged from R10)
// ===========================================================================
template<int MODE>
__global__ __launch_bounds__(256)
void tc_gemm(const float* __restrict__ A,
             const float* __restrict__ w0, const float* __restrict__ w1,
             const float* __restrict__ w2,
             const float* __restrict__ b0, const float* __restrict__ b1,
             const float* __restrict__ b2,
             float* __restrict__ out)
{
    extern __shared__ char dsm[];
    __shared__ float s_bias[128];

    const uint32_t base = (smem_u32(dsm) + 1023u) & ~1023u;
    char* basep = dsm + (base - smem_u32(dsm));

    const int tid  = threadIdx.x;
    const int lane = tid & 31;
    const int wid  = tid >> 5;
    const int z  = blockIdx.z;
    const int n0 = blockIdx.x << 7;
    const int m0 = blockIdx.y << 7;

    const float* W    = (MODE == 1) ? w0 : (z == 0 ? w0 : (z == 1 ? w1 : w2));
    const float* bias = (MODE == 1) ? b0 : (z == 0 ? b0 : (z == 1 ? b1 : b2));
    const float* Ap   = (MODE == 1) ? g_o : A;

    if (tid < 128) s_bias[tid] = bias[n0 + tid];

    const int wm = (wid & 1) << 6;
    const int wn = (wid >> 1) << 5;

    float acc[4][4][4];
    #pragma unroll
    for (int i = 0; i < 4; i++)
        #pragma unroll
        for (int j = 0; j < 4; j++)
            #pragma unroll
            for (int r = 0; r < 4; r++) acc[i][j][r] = 0.0f;

    for (int ck = 0; ck < 16; ck++) {
        const int k0 = ck << 6;
        #pragma unroll
        for (int u = 0; u < 8; u++) {
            const int id = u * 256 + tid;
            const int r  = id >> 4;
            const int c4 = (id & 15) << 2;
            const uint32_t so = swz(r * 128 + c4 * 2);
            {
                float4 v = *(const float4*)(Ap + (size_t)(m0 + r) * 1024 + k0 + c4);
                uint32_t h01, l01, h23, l23;
                cvt2(v.x, v.y, h01, l01);
                cvt2(v.z, v.w, h23, l23);
                *(uint2*)(basep + so)          = make_uint2(h01, h23);
                *(uint2*)(basep + TILE_B + so) = make_uint2(l01, l23);
            }
            {
                float4 v = *(const float4*)(W + (size_t)(n0 + r) * 1024 + k0 + c4);
                uint32_t h01, l01, h23, l23;
                cvt2(v.x, v.y, h01, l01);
                cvt2(v.z, v.w, h23, l23);
                *(uint2*)(basep + 2*TILE_B + so) = make_uint2(h01, h23);
                *(uint2*)(basep + 3*TILE_B + so) = make_uint2(l01, l23);
            }
        }
        __syncthreads();

        for (int ks = 0; ks < 4; ks++) {
            uint32_t ah[4][4], al[4][4];
            {
                const int kc = (ks << 4) + ((lane >> 4) << 3);
                #pragma unroll
                for (int mt = 0; mt < 4; mt++) {
                    const int row = wm + (mt << 4) + (lane & 15);
                    const uint32_t off = swz((uint32_t)(row * 128 + kc * 2));
                    ldsm4(ah[mt], base + off);
                    ldsm4(al[mt], base + TILE_B + off);
                }
            }
            uint32_t bh[4][2], bl[4][2];
            {
                const int kc = (ks << 4) + (lane & 8);
                #pragma unroll
                for (int p = 0; p < 2; p++) {
                    const int n = wn + (p << 4) + (lane & 7) + ((lane & 16) >> 1);
                    const uint32_t off = swz((uint32_t)(n * 128 + kc * 2));
                    uint32_t t[4];
                    ldsm4(t, base + 2*TILE_B + off);
                    bh[2*p][0] = t[0]; bh[2*p][1] = t[1];
                    bh[2*p+1][0] = t[2]; bh[2*p+1][1] = t[3];
                    ldsm4(t, base + 3*TILE_B + off);
                    bl[2*p][0] = t[0]; bl[2*p][1] = t[1];
                    bl[2*p+1][0] = t[2]; bl[2*p+1][1] = t[3];
                }
            }
            #pragma unroll
            for (int mt = 0; mt < 4; mt++)
                #pragma unroll
                for (int nt = 0; nt < 4; nt++) {
                    mma16816(acc[mt][nt], ah[mt], bh[nt]);
                    mma16816(acc[mt][nt], ah[mt], bl[nt]);
                    mma16816(acc[mt][nt], al[mt], bh[nt]);
                }
        }
        __syncthreads();
    }

    #pragma unroll
    for (int mt = 0; mt < 4; mt++) {
        #pragma unroll
        for (int nt = 0; nt < 4; nt++) {
            const int c  = wn + (nt << 3) + ((lane & 3) << 1);
            const int r0 = m0 + wm + (mt << 4) + (lane >> 2);
            #pragma unroll
            for (int half = 0; half < 2; half++) {
                const int row = r0 + half * 8;
                float2 v;
                v.x = acc[mt][nt][half*2+0] + s_bias[c+0];
                v.y = acc[mt][nt][half*2+1] + s_bias[c+1];
                if (MODE == 1) {
                    *(float2*)&out[(size_t)row * 1024 + n0 + c] = v;
                } else {
                    const int bb = row >> 11;
                    const int s  = row & 2047;
                    const int head = (n0 + c) >> 6;
                    const int d    = c & 63;
                    if (z == 2) {
                        __nv_bfloat16 h0 = __float2bfloat16(v.x);
                        __nv_bfloat16 l0 = __float2bfloat16(v.x - __bfloat162float(h0));
                        __nv_bfloat16 h1 = __float2bfloat16(v.y);
                        __nv_bfloat16 l1 = __float2bfloat16(v.y - __bfloat162float(h1));
                        const size_t bi = (((size_t)bb*Hv + head)*DHv) * Sv + s;
                        g_vth[bi + (size_t)d*Sv]       = h0;
                        g_vtl[bi + (size_t)d*Sv]       = l0;
                        g_vth[bi + (size_t)(d+1)*Sv]   = h1;
                        g_vtl[bi + (size_t)(d+1)*Sv]   = l1;
                    } else {
                        float sx = v.x, sy = v.y;
                        if (z == 0) { sx *= 0.125f; sy *= 0.125f; }
                        uint32_t hp, lp;
                        cvt2(sx, sy, hp, lp);
                        const size_t idx = (((size_t)bb*Hv + head)*Sv + s)*DHv + d;
                        if (z == 0) {
                            *(uint32_t*)&g_qh[idx] = hp;
                            *(uint32_t*)&g_ql[idx] = lp;
                        } else {
                            *(uint32_t*)&g_kh[idx] = hp;
                            *(uint32_t*)&g_kl[idx] = lp;
                        }
                    }
                }
            }
        }
    }
}

// ===========================================================================
// Mask all-ones detection
// ===========================================================================
__global__ void mask_flag_init() { g_mall = 1; }
__global__ void mask_flag_reduce(const int* __restrict__ mask, int n4) {
    int ok = 1;
    for (int i = blockIdx.x * blockDim.x + threadIdx.x; i < n4;
         i += gridDim.x * blockDim.x) {
        int4 m = ((const int4*)mask)[i];
        if (!(m.x && m.y && m.z && m.w)) ok = 0;
    }
    if (!ok) atomicExch(&g_mall, 0);
}

// ===========================================================================
// Async tensor-core fused attention, 2 CTAs/SM version.
// CTA = 256 threads, 128-q tile; 8 warps x 16q strips. K chunks of 64 keys,
// 2-stage cp.async pipeline. Q fragments register-resident.
// Smem: Qh/Ql 2x16KB + 2 stages x 32KB (Kh|Kl|Vth|Vtl 8KB each) ~= 99KB.
// ===========================================================================
#define AQH 0
#define AQL 16384
#define AST 32768
#define STG_B 32768
#define ARS (AST + 2*STG_B)          // 98304
#define ATTN_SMEM (ARS + 1024 + 1024)

__global__ __launch_bounds__(256, 2)
void attn_tc(const int* __restrict__ mask, float* __restrict__ attn)
{
    extern __shared__ char dsm[];
    __shared__ int s_mall;
    const uint32_t base = (smem_u32(dsm) + 1023u) & ~1023u;
    char* basep = dsm + (base - smem_u32(dsm));
    float* s_rinv = (float*)(basep + ARS);

    const int tid  = threadIdx.x;
    const int lane = tid & 31;
    const int wq   = tid >> 5;              // warp -> 16-query strip (0..7)
    const int q0g  = blockIdx.x << 7;       // 128-q tile
    const int h = blockIdx.y, b = blockIdx.z;
    const size_t bh = (size_t)b * Hv + h;

    const __nv_bfloat16* qhp = g_qh + (bh * Sv + q0g) * DHv;
    const __nv_bfloat16* qlp = g_ql + (bh * Sv + q0g) * DHv;
    const __nv_bfloat16* khp = g_kh + bh * Sv * DHv;
    const __nv_bfloat16* klp = g_kl + bh * Sv * DHv;
    const __nv_bfloat16* vhp = g_vth + bh * (size_t)DHv * Sv;
    const __nv_bfloat16* vlp = g_vtl + bh * (size_t)DHv * Sv;
    float* abase = attn + (bh * Sv + q0g) * Sv;
    const int* mbase = mask + ((size_t)b * Sv + q0g) * Sv;

    if (tid == 0) s_mall = g_mall;

    // ---- Q tile async copy: 128 rows x 8 granules per plane  (group 0)
    #pragma unroll
    for (int u = 0; u < 4; u++) {
        const int g = u * 256 + tid;       // 0..1023
        const int row = g >> 3, c16 = g & 7;
        const uint32_t so = swz((uint32_t)(row * 128 + c16 * 16));
        CP16(base + AQH + so, qhp + (size_t)row * DHv + c16 * 8);
        CP16(base + AQL + so, qlp + (size_t)row * DHv + c16 * 8);
    }
    CP_COMMIT();

    auto fill = [&](int kt, int st) {
        const int k0 = kt << 6;
        const uint32_t sb = base + AST + st * STG_B;
        #pragma unroll
        for (int u = 0; u < 2; u++) {
            const int id = u * 256 + tid;          // 0..511
            const int row = id >> 3, c16 = id & 7; // 64 rows x 8 granules
            const uint32_t so = swz((uint32_t)(row * 128 + c16 * 16));
            CP16(sb + 0     + so, khp + (size_t)(k0 + row) * DHv + c16 * 8);
            CP16(sb + 8192  + so, klp + (size_t)(k0 + row) * DHv + c16 * 8);
            CP16(sb + 16384 + so, vhp + (size_t)row * Sv + k0 + c16 * 8);
            CP16(sb + 24576 + so, vlp + (size_t)row * Sv + k0 + c16 * 8);
        }
    };
    fill(0, 0); CP_COMMIT();
    fill(1, 1); CP_COMMIT();

    // ---- Q fragments -> registers while stage 0 lands
    CP_WAIT(2);                 // Q group done
    __syncthreads();
    uint32_t qh[4][4], ql[4][4];
    #pragma unroll
    for (int ks = 0; ks < 4; ks++) {
        const int row = (wq << 4) + (lane & 15);
        const int kc  = (ks << 4) + ((lane >> 4) << 3);
        const uint32_t off = swz((uint32_t)(row * 128 + kc * 2));
        ldsm4(qh[ks], base + AQH + off);
        ldsm4(ql[ks], base + AQL + off);
    }

    float o[8][4];
    #pragma unroll
    for (int i = 0; i < 8; i++)
        #pragma unroll
        for (int j = 0; j < 4; j++) o[i][j] = 0.0f;
    float rs0 = 0.0f, rs1 = 0.0f;

    const int r0 = lane >> 2;
    const int c0 = (lane & 3) << 1;
    const int qa = (wq << 4) + r0;

    for (int kt = 0; kt < 32; kt++) {
        CP_WAIT(1);
        __syncthreads();
        const uint32_t sb = base + AST + (kt & 1) * STG_B;
        const int k0 = kt << 6;
        const int mall = s_mall;

        #pragma unroll
        for (int hf = 0; hf < 2; hf++) {           // 32-key halves
            float sc[4][4];
            #pragma unroll
            for (int i = 0; i < 4; i++)
                #pragma unroll
                for (int j = 0; j < 4; j++) sc[i][j] = 0.0f;

            #pragma unroll
            for (int ks = 0; ks < 4; ks++) {
                const int kc = (ks << 4) + (lane & 8);
                #pragma unroll
                for (int p = 0; p < 2; p++) {
                    const int n = (hf << 5) + (p << 4) + (lane & 7) + ((lane & 16) >> 1);
                    const uint32_t off = swz((uint32_t)(n * 128 + kc * 2));
                    uint32_t th[4], tl[4];
                    ldsm4(th, sb + 0 + off);
                    ldsm4(tl, sb + 8192 + off);
                    uint32_t bh0[2] = {th[0], th[1]}, bh1[2] = {th[2], th[3]};
                    uint32_t bl0[2] = {tl[0], tl[1]}, bl1[2] = {tl[2], tl[3]};
                    mma16816(sc[2*p],   qh[ks], bh0);
                    mma16816(sc[2*p],   qh[ks], bl0);
                    mma16816(sc[2*p],   ql[ks], bh0);
                    mma16816(sc[2*p+1], qh[ks], bh1);
                    mma16816(sc[2*p+1], qh[ks], bl1);
                    mma16816(sc[2*p+1], ql[ks], bh1);
                }
            }

            // ---- exp + mask + unnormalized attn store + rowsum
            #pragma unroll
            for (int nt = 0; nt < 4; nt++) {
                const int kcol = k0 + (hf << 5) + (nt << 3) + c0;
                float e0 = fexp(sc[nt][0]);
                float e1 = fexp(sc[nt][1]);
                float e2 = fexp(sc[nt][2]);
                float e3 = fexp(sc[nt][3]);
                if (!mall) {
                    int2 m0 = *(const int2*)&mbase[(size_t)qa * Sv + kcol];
                    int2 m1 = *(const int2*)&mbase[(size_t)(qa + 8) * Sv + kcol];
                    e0 = m0.x ? e0 : 0.0f;
                    e1 = m0.y ? e1 : 0.0f;
                    e2 = m1.x ? e2 : 0.0f;
                    e3 = m1.y ? e3 : 0.0f;
                }
                *(float2*)&abase[(size_t)qa * Sv + kcol]       = make_float2(e0, e1);
                *(float2*)&abase[(size_t)(qa + 8) * Sv + kcol] = make_float2(e2, e3);
                rs0 += e0 + e1;
                rs1 += e2 + e3;
                sc[nt][0] = e0; sc[nt][1] = e1; sc[nt][2] = e2; sc[nt][3] = e3;
            }

            // ---- E @ V^T: accumulate O over this half's 32 keys
            #pragma unroll
            for (int j = 0; j < 2; j++) {
                uint32_t eh[4], el[4];
                cvt2(sc[2*j][0],   sc[2*j][1],   eh[0], el[0]);
                cvt2(sc[2*j][2],   sc[2*j][3],   eh[1], el[1]);
                cvt2(sc[2*j+1][0], sc[2*j+1][1], eh[2], el[2]);
                cvt2(sc[2*j+1][2], sc[2*j+1][3], eh[3], el[3]);
                const int kc = (hf << 5) + (j << 4) + (lane & 8);
                #pragma unroll
                for (int p = 0; p < 4; p++) {
                    const int n = (p << 4) + (lane & 7) + ((lane & 16) >> 1);
                    const uint32_t off = swz((uint32_t)(n * 128 + kc * 2));
                    uint32_t th[4], tl[4];
                    ldsm4(th, sb + 16384 + off);
                    ldsm4(tl, sb + 24576 + off);
                    uint32_t bh0[2] = {th[0], th[1]}, bh1[2] = {th[2], th[3]};
                    uint32_t bl0[2] = {tl[0], tl[1]}, bl1[2] = {tl[2], tl[3]};
                    mma16816(o[2*p],   eh, bh0);
                    mma16816(o[2*p],   eh, bl0);
                    mma16816(o[2*p],   el, bh0);
                    mma16816(o[2*p+1], eh, bh1);
                    mma16816(o[2*p+1], eh, bl1);
                    mma16816(o[2*p+1], el, bh1);
                }
            }
        }

        __syncthreads();
        if (kt + 2 < 32) fill(kt + 2, kt & 1);
        CP_COMMIT();
    }

    // ---- rowsum reduce within quad
    rs0 += __shfl_xor_sync(0xFFFFFFFF, rs0, 1);
    rs0 += __shfl_xor_sync(0xFFFFFFFF, rs0, 2);
    rs1 += __shfl_xor_sync(0xFFFFFFFF, rs1, 1);
    rs1 += __shfl_xor_sync(0xFFFFFFFF, rs1, 2);
    const float ri0 = 1.0f / rs0;
    const float ri1 = 1.0f / rs1;
    if ((lane & 3) == 0) {
        s_rinv[qa]     = ri0;
        s_rinv[qa + 8] = ri1;
    }

    // ---- normalized O -> g_o [b, s, D]
    #pragma unroll
    for (int nt = 0; nt < 8; nt++) {
        const int d = (nt << 3) + c0;
        float* dst0 = &g_o[((size_t)b * Sv + q0g + qa) * Dv + (h << 6) + d];
        float* dst8 = &g_o[((size_t)b * Sv + q0g + qa + 8) * Dv + (h << 6) + d];
        *(float2*)dst0 = make_float2(o[nt][0] * ri0, o[nt][1] * ri0);
        *(float2*)dst8 = make_float2(o[nt][2] * ri1, o[nt][3] * ri1);
    }
    __syncthreads();

    // ---- rescale attn strip in place (fresh writes -> L2 hits)
    for (int it = 0; it < 256; it++) {
        const int g = it * 256 + tid;       // 128 rows x 512 float4
        const int row = g >> 9;
        const int c4  = (g & 511) << 2;
        const float inv = s_rinv[row];
        float4 v = *(float4*)&abase[(size_t)row * Sv + c4];
        v.x *= inv; v.y *= inv; v.z *= inv; v.w *= inv;
        *(float4*)&abase[(size_t)row * Sv + c4] = v;
    }
}

// ---------------------------------------------------------------------------
extern "C" void kernel_launch(void* const* d_in, const int* in_sizes, int n_in,
                              void* d_out, int out_size)
{
    const float* x    = (const float*)d_in[0];
    const int*   mask = (const int*)  d_in[1];
    const float* wq_w = (const float*)d_in[2];
    const float* wq_b = (const float*)d_in[3];
    const float* wk_w = (const float*)d_in[4];
    const float* wk_b = (const float*)d_in[5];
    const float* wv_w = (const float*)d_in[6];
    const float* wv_b = (const float*)d_in[7];
    const float* wo_w = (const float*)d_in[8];
    const float* wo_b = (const float*)d_in[9];

    float* out  = (float*)d_out;
    float* attn = out + (size_t)NTv * Dv;   // outputs concatenated: out, then attn

    cudaFuncSetAttribute(attn_tc, cudaFuncAttributeMaxDynamicSharedMemorySize,
                         ATTN_SMEM);
    cudaFuncSetAttribute(tc_gemm<0>, cudaFuncAttributeMaxDynamicSharedMemorySize,
                         GEMM_SMEM);
    cudaFuncSetAttribute(tc_gemm<1>, cudaFuncAttributeMaxDynamicSharedMemorySize,
                         GEMM_SMEM);

    mask_flag_init<<<1, 1>>>();
    mask_flag_reduce<<<1024, 256>>>(mask, (Bv * Sv * Sv) / 4);

    tc_gemm<0><<<dim3(8, 32, 3), 256, GEMM_SMEM>>>(
        x, wq_w, wk_w, wv_w, wq_b, wk_b, wv_b, nullptr);
    attn_tc<<<dim3(Sv / 128, Hv, Bv), 256, ATTN_SMEM>>>(mask, attn);
    tc_gemm<1><<<dim3(8, 32, 1), 256, GEMM_SMEM>>>(
        nullptr, wo_w, nullptr, nullptr, wo_b, nullptr, nullptr, out);
}

// round 15
// speedup vs baseline: 1.0305x; 1.0305x over previous
#include <cuda_runtime.h>
#include <cuda_bf16.h>
#include <cstdint>

#define Bv 2
#define Sv 2048
#define Dv 1024
#define Hv 16
#define DHv 64
#define NTv (Bv*Sv)

// Scratch (static device globals; allocation-free at launch time)
__device__ float g_o[(size_t)NTv*Dv];         // attn@V in [b,s,D] layout
__device__ int   g_mall;                      // 1 if mask is all-nonzero
// bf16 hi/lo planes produced by the QKV GEMM epilogue
__device__ __nv_bfloat16 g_qh[(size_t)Bv*Hv*Sv*DHv];  // [b,h,s,d], pre-scaled 0.125
__device__ __nv_bfloat16 g_ql[(size_t)Bv*Hv*Sv*DHv];
__device__ __nv_bfloat16 g_kh[(size_t)Bv*Hv*Sv*DHv];  // [b,h,s,d]
__device__ __nv_bfloat16 g_kl[(size_t)Bv*Hv*Sv*DHv];
__device__ __nv_bfloat16 g_vth[(size_t)Bv*Hv*Sv*DHv]; // [b,h,d,s] (transposed)
__device__ __nv_bfloat16 g_vtl[(size_t)Bv*Hv*Sv*DHv];

// ===========================================================================
// Helpers
// ===========================================================================
__device__ __forceinline__ uint32_t smem_u32(const void* p) {
    uint32_t a;
    asm("{ .reg .u64 t; cvta.to.shared.u64 t, %1; cvt.u32.u64 %0, t; }"
        : "=r"(a) : "l"(p));
    return a;
}
__device__ __forceinline__ uint32_t swz(uint32_t off) {
    return off ^ ((off >> 3) & 0x70);
}
__device__ __forceinline__ void ldsm4(uint32_t* r, uint32_t addr) {
    asm volatile("ldmatrix.sync.aligned.m8n8.x4.shared.b16 {%0,%1,%2,%3}, [%4];"
                 : "=r"(r[0]), "=r"(r[1]), "=r"(r[2]), "=r"(r[3]) : "r"(addr));
}
__device__ __forceinline__ void mma16816(float* c, const uint32_t* a, const uint32_t* b) {
    asm volatile(
        "mma.sync.aligned.m16n8k16.row.col.f32.bf16.bf16.f32 "
        "{%0,%1,%2,%3}, {%4,%5,%6,%7}, {%8,%9}, {%0,%1,%2,%3};"
        : "+f"(c[0]), "+f"(c[1]), "+f"(c[2]), "+f"(c[3])
        : "r"(a[0]), "r"(a[1]), "r"(a[2]), "r"(a[3]), "r"(b[0]), "r"(b[1]));
}
__device__ __forceinline__ void cvt2(float x, float y, uint32_t& hp, uint32_t& lp) {
    __nv_bfloat16 hx = __float2bfloat16(x);
    __nv_bfloat16 hy = __float2bfloat16(y);
    __nv_bfloat16 lx = __float2bfloat16(x - __bfloat162float(hx));
    __nv_bfloat16 ly = __float2bfloat16(y - __bfloat162float(hy));
    hp = ((uint32_t)__bfloat16_as_ushort(hy) << 16) | __bfloat16_as_ushort(hx);
    lp = ((uint32_t)__bfloat16_as_ushort(ly) << 16) | __bfloat16_as_ushort(lx);
}
// FMA-pipe exp (no MUFU)
__device__ __forceinline__ float fexp(float x) {
    float z  = fmaf(x, 1.4426950408889634f, 12582912.0f);
    int   i  = __float_as_int(z);
    float fi = z - 12582912.0f;
    float f  = fmaf(x, 1.4426950408889634f, -fi);
    float p  = 1.5403530e-4f;
    p = fmaf(p, f, 1.3333558e-3f);
    p = fmaf(p, f, 9.6181291e-3f);
    p = fmaf(p, f, 5.5504109e-2f);
    p = fmaf(p, f, 2.4022651e-1f);
    p = fmaf(p, f, 6.9314718e-1f);
    p = fmaf(p, f, 1.0f);
    return __int_as_float(__float_as_int(p) + (i << 23));
}
#define CP16(dst, src) \
    asm volatile("cp.async.cg.shared.global [%0], [%1], 16;" \
                 :: "r"(dst), "l"(src) : "memory")
#define CP_COMMIT() asm volatile("cp.async.commit_group;" ::: "memory")
#define CP_WAIT(n)  asm volatile("cp.async.wait_group %0;" :: "n"(n) : "memory")

#define TILE_B 16384
#define GEMM_SMEM (4*TILE_B + 1024)

// ===========================================================================
// HMMA bf16x3 GEMM: Y = A @ W^T + bias (unchanged)
// ===========================================================================
template<int MODE>
__global__ __launch_bounds__(256)
void tc_gemm(const float* __restrict__ A,
             const float* __restrict__ w0, const float* __restrict__ w1,
             const float* __restrict__ w2,
             const float* __restrict__ b0, const float* __restrict__ b1,
             const float* __restrict__ b2,
             float* __restrict__ out)
{
    extern __shared__ char dsm[];
    __shared__ float s_bias[128];

    const uint32_t base = (smem_u32(dsm) + 1023u) & ~1023u;
    char* basep = dsm + (base - smem_u32(dsm));

    const int tid  = threadIdx.x;
    const int lane = tid & 31;
    const int wid  = tid >> 5;
    const int z  = blockIdx.z;
    const int n0 = blockIdx.x << 7;
    const int m0 = blockIdx.y << 7;

    const float* W    = (MODE == 1) ? w0 : (z == 0 ? w0 : (z == 1 ? w1 : w2));
    const float* bias = (MODE == 1) ? b0 : (z == 0 ? b0 : (z == 1 ? b1 : b2));
    const float* Ap   = (MODE == 1) ? g_o : A;

    if (tid < 128) s_bias[tid] = bias[n0 + tid];

    const int wm = (wid & 1) << 6;
    const int wn = (wid >> 1) << 5;

    float acc[4][4][4];
    #pragma unroll
    for (int i = 0; i < 4; i++)
        #pragma unroll
        for (int j = 0; j < 4; j++)
            #pragma unroll
            for (int r = 0; r < 4; r++) acc[i][j][r] = 0.0f;

    for (int ck = 0; ck < 16; ck++) {
        const int k0 = ck << 6;
        #pragma unroll
        for (int u = 0; u < 8; u++) {
            const int id = u * 256 + tid;
            const int r  = id >> 4;
            const int c4 = (id & 15) << 2;
            const uint32_t so = swz(r * 128 + c4 * 2);
            {
                float4 v = *(const float4*)(Ap + (size_t)(m0 + r) * 1024 + k0 + c4);
                uint32_t h01, l01, h23, l23;
                cvt2(v.x, v.y, h01, l01);
                cvt2(v.z, v.w, h23, l23);
                *(uint2*)(basep + so)          = make_uint2(h01, h23);
                *(uint2*)(basep + TILE_B + so) = make_uint2(l01, l23);
            }
            {
                float4 v = *(const float4*)(W + (size_t)(n0 + r) * 1024 + k0 + c4);
                uint32_t h01, l01, h23, l23;
                cvt2(v.x, v.y, h01, l01);
                cvt2(v.z, v.w, h23, l23);
                *(uint2*)(basep + 2*TILE_B + so) = make_uint2(h01, h23);
                *(uint2*)(basep + 3*TILE_B + so) = make_uint2(l01, l23);
            }
        }
        __syncthreads();

        for (int ks = 0; ks < 4; ks++) {
            uint32_t ah[4][4], al[4][4];
            {
                const int kc = (ks << 4) + ((lane >> 4) << 3);
                #pragma unroll
                for (int mt = 0; mt < 4; mt++) {
                    const int row = wm + (mt << 4) + (lane & 15);
                    const uint32_t off = swz((uint32_t)(row * 128 + kc * 2));
                    ldsm4(ah[mt], base + off);
                    ldsm4(al[mt], base + TILE_B + off);
                }
            }
            uint32_t bh[4][2], bl[4][2];
            {
                const int kc = (ks << 4) + (lane & 8);
                #pragma unroll
                for (int p = 0; p < 2; p++) {
                    const int n = wn + (p << 4) + (lane & 7) + ((lane & 16) >> 1);
                    const uint32_t off = swz((uint32_t)(n * 128 + kc * 2));
                    uint32_t t[4];
                    ldsm4(t, base + 2*TILE_B + off);
                    bh[2*p][0] = t[0]; bh[2*p][1] = t[1];
                    bh[2*p+1][0] = t[2]; bh[2*p+1][1] = t[3];
                    ldsm4(t, base + 3*TILE_B + off);
                    bl[2*p][0] = t[0]; bl[2*p][1] = t[1];
                    bl[2*p+1][0] = t[2]; bl[2*p+1][1] = t[3];
                }
            }
            #pragma unroll
            for (int mt = 0; mt < 4; mt++)
                #pragma unroll
                for (int nt = 0; nt < 4; nt++) {
                    mma16816(acc[mt][nt], ah[mt], bh[nt]);
                    mma16816(acc[mt][nt], ah[mt], bl[nt]);
                    mma16816(acc[mt][nt], al[mt], bh[nt]);
                }
        }
        __syncthreads();
    }

    #pragma unroll
    for (int mt = 0; mt < 4; mt++) {
        #pragma unroll
        for (int nt = 0; nt < 4; nt++) {
            const int c  = wn + (nt << 3) + ((lane & 3) << 1);
            const int r0 = m0 + wm + (mt << 4) + (lane >> 2);
            #pragma unroll
            for (int half = 0; half < 2; half++) {
                const int row = r0 + half * 8;
                float2 v;
                v.x = acc[mt][nt][half*2+0] + s_bias[c+0];
                v.y = acc[mt][nt][half*2+1] + s_bias[c+1];
                if (MODE == 1) {
                    *(float2*)&out[(size_t)row * 1024 + n0 + c] = v;
                } else {
                    const int bb = row >> 11;
                    const int s  = row & 2047;
                    const int head = (n0 + c) >> 6;
                    const int d    = c & 63;
                    if (z == 2) {
                        __nv_bfloat16 h0 = __float2bfloat16(v.x);
                        __nv_bfloat16 l0 = __float2bfloat16(v.x - __bfloat162float(h0));
                        __nv_bfloat16 h1 = __float2bfloat16(v.y);
                        __nv_bfloat16 l1 = __float2bfloat16(v.y - __bfloat162float(h1));
                        const size_t bi = (((size_t)bb*Hv + head)*DHv) * Sv + s;
                        g_vth[bi + (size_t)d*Sv]       = h0;
                        g_vtl[bi + (size_t)d*Sv]       = l0;
                        g_vth[bi + (size_t)(d+1)*Sv]   = h1;
                        g_vtl[bi + (size_t)(d+1)*Sv]   = l1;
                    } else {
                        float sx = v.x, sy = v.y;
                        if (z == 0) { sx *= 0.125f; sy *= 0.125f; }
                        uint32_t hp, lp;
                        cvt2(sx, sy, hp, lp);
                        const size_t idx = (((size_t)bb*Hv + head)*Sv + s)*DHv + d;
                        if (z == 0) {
                            *(uint32_t*)&g_qh[idx] = hp;
                            *(uint32_t*)&g_ql[idx] = lp;
                        } else {
                            *(uint32_t*)&g_kh[idx] = hp;
                            *(uint32_t*)&g_kl[idx] = lp;
                        }
                    }
                }
            }
        }
    }
}

// ===========================================================================
// Mask all-ones detection
// ===========================================================================
__global__ void mask_flag_init() { g_mall = 1; }
__global__ void mask_flag_reduce(const int* __restrict__ mask, int n4) {
    int ok = 1;
    for (int i = blockIdx.x * blockDim.x + threadIdx.x; i < n4;
         i += gridDim.x * blockDim.x) {
        int4 m = ((const int4*)mask)[i];
        if (!(m.x && m.y && m.z && m.w)) ok = 0;
    }
    if (!ok) atomicExch(&g_mall, 0);
}

// ===========================================================================
// Two-pass async tensor-core fused attention (write-once attn).
// CTA = 256 threads, 128-q tile; 8 warps x 16q strips.
// Phase A: K-only 4-stage pipeline -> rowsums. Phase B: K+V 2-stage pipeline,
// recompute identical scores, write NORMALIZED attn once, E@V with
// normalized E (no final O scale, no rescale pass).
// Smem: Qh/Ql 2x16KB + 64KB stage region (A: 4x16KB K; B: 2x32KB K+V).
// ===========================================================================
#define AQH 0
#define AQL 16384
#define AST 32768
#define ATTN_SMEM (32768 + 65536 + 2048)

__global__ __launch_bounds__(256, 2)
void attn_tc(const int* __restrict__ mask, float* __restrict__ attn)
{
    extern __shared__ char dsm[];
    __shared__ int s_mall;
    const uint32_t base = (smem_u32(dsm) + 1023u) & ~1023u;

    const int tid  = threadIdx.x;
    const int lane = tid & 31;
    const int wq   = tid >> 5;              // warp -> 16-query strip (0..7)
    const int q0g  = blockIdx.x << 7;       // 128-q tile
    const int h = blockIdx.y, b = blockIdx.z;
    const size_t bh = (size_t)b * Hv + h;

    const __nv_bfloat16* qhp = g_qh + (bh * Sv + q0g) * DHv;
    const __nv_bfloat16* qlp = g_ql + (bh * Sv + q0g) * DHv;
    const __nv_bfloat16* khp = g_kh + bh * Sv * DHv;
    const __nv_bfloat16* klp = g_kl + bh * Sv * DHv;
    const __nv_bfloat16* vhp = g_vth + bh * (size_t)DHv * Sv;
    const __nv_bfloat16* vlp = g_vtl + bh * (size_t)DHv * Sv;
    float* abase = attn + (bh * Sv + q0g) * Sv;
    const int* mbase = mask + ((size_t)b * Sv + q0g) * Sv;

    if (tid == 0) s_mall = g_mall;

    // ---- Q tile async copy (its own group)
    #pragma unroll
    for (int u = 0; u < 4; u++) {
        const int g = u * 256 + tid;       // 0..1023
        const int row = g >> 3, c16 = g & 7;
        const uint32_t so = swz((uint32_t)(row * 128 + c16 * 16));
        CP16(base + AQH + so, qhp + (size_t)row * DHv + c16 * 8);
        CP16(base + AQL + so, qlp + (size_t)row * DHv + c16 * 8);
    }
    CP_COMMIT();

    // Phase A fill: K planes only, 16KB stages (4 deep)
    auto fillA = [&](int kt, int st) {
        const int k0 = kt << 6;
        const uint32_t sb = base + AST + st * 16384;
        #pragma unroll
        for (int u = 0; u < 2; u++) {
            const int id = u * 256 + tid;          // 0..511
            const int row = id >> 3, c16 = id & 7;
            const uint32_t so = swz((uint32_t)(row * 128 + c16 * 16));
            CP16(sb + 0    + so, khp + (size_t)(k0 + row) * DHv + c16 * 8);
            CP16(sb + 8192 + so, klp + (size_t)(k0 + row) * DHv + c16 * 8);
        }
    };
    fillA(0, 0); CP_COMMIT();
    fillA(1, 1); CP_COMMIT();
    fillA(2, 2); CP_COMMIT();

    // ---- Q fragments -> registers
    CP_WAIT(3);
    __syncthreads();
    uint32_t qh[4][4], ql[4][4];
    #pragma unroll
    for (int ks = 0; ks < 4; ks++) {
        const int row = (wq << 4) + (lane & 15);
        const int kc  = (ks << 4) + ((lane >> 4) << 3);
        const uint32_t off = swz((uint32_t)(row * 128 + kc * 2));
        ldsm4(qh[ks], base + AQH + off);
        ldsm4(ql[ks], base + AQL + off);
    }

    const int r0 = lane >> 2;
    const int c0 = (lane & 3) << 1;
    const int qa = (wq << 4) + r0;
    const int mall = s_mall;

    float rs0 = 0.0f, rs1 = 0.0f;

    // =================== Phase A: rowsums only ===================
    for (int kt = 0; kt < 32; kt++) {
        CP_WAIT(2);
        __syncthreads();
        const uint32_t sb = base + AST + (kt & 3) * 16384;
        const int k0 = kt << 6;

        #pragma unroll
        for (int hf = 0; hf < 2; hf++) {
            float sc[4][4];
            #pragma unroll
            for (int i = 0; i < 4; i++)
                #pragma unroll
                for (int j = 0; j < 4; j++) sc[i][j] = 0.0f;

            #pragma unroll
            for (int ks = 0; ks < 4; ks++) {
                const int kc = (ks << 4) + (lane & 8);
                #pragma unroll
                for (int p = 0; p < 2; p++) {
                    const int n = (hf << 5) + (p << 4) + (lane & 7) + ((lane & 16) >> 1);
                    const uint32_t off = swz((uint32_t)(n * 128 + kc * 2));
                    uint32_t th[4], tl[4];
                    ldsm4(th, sb + 0 + off);
                    ldsm4(tl, sb + 8192 + off);
                    uint32_t bh0[2] = {th[0], th[1]}, bh1[2] = {th[2], th[3]};
                    uint32_t bl0[2] = {tl[0], tl[1]}, bl1[2] = {tl[2], tl[3]};
                    mma16816(sc[2*p],   qh[ks], bh0);
                    mma16816(sc[2*p],   qh[ks], bl0);
                    mma16816(sc[2*p],   ql[ks], bh0);
                    mma16816(sc[2*p+1], qh[ks], bh1);
                    mma16816(sc[2*p+1], qh[ks], bl1);
                    mma16816(sc[2*p+1], ql[ks], bh1);
                }
            }

            #pragma unroll
            for (int nt = 0; nt < 4; nt++) {
                const int kcol = k0 + (hf << 5) + (nt << 3) + c0;
                float e0 = fexp(sc[nt][0]);
                float e1 = fexp(sc[nt][1]);
                float e2 = fexp(sc[nt][2]);
                float e3 = fexp(sc[nt][3]);
                if (!mall) {
                    int2 m0 = *(const int2*)&mbase[(size_t)qa * Sv + kcol];
                    int2 m1 = *(const int2*)&mbase[(size_t)(qa + 8) * Sv + kcol];
                    e0 = m0.x ? e0 : 0.0f;
                    e1 = m0.y ? e1 : 0.0f;
                    e2 = m1.x ? e2 : 0.0f;
                    e3 = m1.y ? e3 : 0.0f;
                }
                rs0 += e0 + e1;
                rs1 += e2 + e3;
            }
        }

        if (kt + 3 < 32) fillA(kt + 3, (kt + 3) & 3);
        CP_COMMIT();
    }

    // ---- rowsum reduce within quad -> per-thread inverses
    rs0 += __shfl_xor_sync(0xFFFFFFFF, rs0, 1);
    rs0 += __shfl_xor_sync(0xFFFFFFFF, rs0, 2);
    rs1 += __shfl_xor_sync(0xFFFFFFFF, rs1, 1);
    rs1 += __shfl_xor_sync(0xFFFFFFFF, rs1, 2);
    const float ri0 = 1.0f / rs0;
    const float ri1 = 1.0f / rs1;

    // =================== Phase B: normalized write + E@V ===================
    CP_WAIT(0);
    __syncthreads();

    auto fillB = [&](int kt, int st) {
        const int k0 = kt << 6;
        const uint32_t sb = base + AST + st * 32768;
        #pragma unroll
        for (int u = 0; u < 2; u++) {
            const int id = u * 256 + tid;
            const int row = id >> 3, c16 = id & 7;
            const uint32_t so = swz((uint32_t)(row * 128 + c16 * 16));
            CP16(sb + 0     + so, khp + (size_t)(k0 + row) * DHv + c16 * 8);
            CP16(sb + 8192  + so, klp + (size_t)(k0 + row) * DHv + c16 * 8);
            CP16(sb + 16384 + so, vhp + (size_t)row * Sv + k0 + c16 * 8);
            CP16(sb + 24576 + so, vlp + (size_t)row * Sv + k0 + c16 * 8);
        }
    };
    fillB(0, 0); CP_COMMIT();
    fillB(1, 1); CP_COMMIT();

    float o[8][4];
    #pragma unroll
    for (int i = 0; i < 8; i++)
        #pragma unroll
        for (int j = 0; j < 4; j++) o[i][j] = 0.0f;

    for (int kt = 0; kt < 32; kt++) {
        CP_WAIT(1);
        __syncthreads();
        const uint32_t sb = base + AST + (kt & 1) * 32768;
        const int k0 = kt << 6;

        #pragma unroll
        for (int hf = 0; hf < 2; hf++) {
            float sc[4][4];
            #pragma unroll
            for (int i = 0; i < 4; i++)
                #pragma unroll
                for (int j = 0; j < 4; j++) sc[i][j] = 0.0f;

            #pragma unroll
            for (int ks = 0; ks < 4; ks++) {
                const int kc = (ks << 4) + (lane & 8);
                #pragma unroll
                for (int p = 0; p < 2; p++) {
                    const int n = (hf << 5) + (p << 4) + (lane & 7) + ((lane & 16) >> 1);
                    const uint32_t off = swz((uint32_t)(n * 128 + kc * 2));
                    uint32_t th[4], tl[4];
                    ldsm4(th, sb + 0 + off);
                    ldsm4(tl, sb + 8192 + off);
                    uint32_t bh0[2] = {th[0], th[1]}, bh1[2] = {th[2], th[3]};
                    uint32_t bl0[2] = {tl[0], tl[1]}, bl1[2] = {tl[2], tl[3]};
                    mma16816(sc[2*p],   qh[ks], bh0);
                    mma16816(sc[2*p],   qh[ks], bl0);
                    mma16816(sc[2*p],   ql[ks], bh0);
                    mma16816(sc[2*p+1], qh[ks], bh1);
                    mma16816(sc[2*p+1], qh[ks], bl1);
                    mma16816(sc[2*p+1], ql[ks], bh1);
                }
            }

            // ---- exp + mask + NORMALIZE + single attn store
            #pragma unroll
            for (int nt = 0; nt < 4; nt++) {
                const int kcol = k0 + (hf << 5) + (nt << 3) + c0;
                float e0 = fexp(sc[nt][0]);
                float e1 = fexp(sc[nt][1]);
                float e2 = fexp(sc[nt][2]);
                float e3 = fexp(sc[nt][3]);
                if (!mall) {
                    int2 m0 = *(const int2*)&mbase[(size_t)qa * Sv + kcol];
                    int2 m1 = *(const int2*)&mbase[(size_t)(qa + 8) * Sv + kcol];
                    e0 = m0.x ? e0 : 0.0f;
                    e1 = m0.y ? e1 : 0.0f;
                    e2 = m1.x ? e2 : 0.0f;
                    e3 = m1.y ? e3 : 0.0f;
                }
                e0 *= ri0; e1 *= ri0; e2 *= ri1; e3 *= ri1;
                *(float2*)&abase[(size_t)qa * Sv + kcol]       = make_float2(e0, e1);
                *(float2*)&abase[(size_t)(qa + 8) * Sv + kcol] = make_float2(e2, e3);
                sc[nt][0] = e0; sc[nt][1] = e1; sc[nt][2] = e2; sc[nt][3] = e3;
            }

            // ---- E @ V^T with normalized E
            #pragma unroll
            for (int j = 0; j < 2; j++) {
                uint32_t eh[4], el[4];
                cvt2(sc[2*j][0],   sc[2*j][1],   eh[0], el[0]);
                cvt2(sc[2*j][2],   sc[2*j][3],   eh[1], el[1]);
                cvt2(sc[2*j+1][0], sc[2*j+1][1], eh[2], el[2]);
                cvt2(sc[2*j+1][2], sc[2*j+1][3], eh[3], el[3]);
                const int kc = (hf << 5) + (j << 4) + (lane & 8);
                #pragma unroll
                for (int p = 0; p < 4; p++) {
                    const int n = (p << 4) + (lane & 7) + ((lane & 16) >> 1);
                    const uint32_t off = swz((uint32_t)(n * 128 + kc * 2));
                    uint32_t th[4], tl[4];
                    ldsm4(th, sb + 16384 + off);
                    ldsm4(tl, sb + 24576 + off);
                    uint32_t bh0[2] = {th[0], th[1]}, bh1[2] = {th[2], th[3]};
                    uint32_t bl0[2] = {tl[0], tl[1]}, bl1[2] = {tl[2], tl[3]};
                    mma16816(o[2*p],   eh, bh0);
                    mma16816(o[2*p],   eh, bl0);
                    mma16816(o[2*p],   el, bh0);
                    mma16816(o[2*p+1], eh, bh1);
                    mma16816(o[2*p+1], eh, bl1);
                    mma16816(o[2*p+1], el, bh1);
                }
            }
        }

        __syncthreads();
        if (kt + 2 < 32) fillB(kt + 2, kt & 1);
        CP_COMMIT();
    }

    // ---- O (already normalized) -> g_o [b, s, D]
    #pragma unroll
    for (int nt = 0; nt < 8; nt++) {
        const int d = (nt << 3) + c0;
        float* dst0 = &g_o[((size_t)b * Sv + q0g + qa) * Dv + (h << 6) + d];
        float* dst8 = &g_o[((size_t)b * Sv + q0g + qa + 8) * Dv + (h << 6) + d];
        *(float2*)dst0 = make_float2(o[nt][0], o[nt][1]);
        *(float2*)dst8 = make_float2(o[nt][2], o[nt][3]);
    }
}

// ---------------------------------------------------------------------------
extern "C" void kernel_launch(void* const* d_in, const int* in_sizes, int n_in,
                              void* d_out, int out_size)
{
    const float* x    = (const float*)d_in[0];
    const int*   mask = (const int*)  d_in[1];
    const float* wq_w = (const float*)d_in[2];
    const float* wq_b = (const float*)d_in[3];
    const float* wk_w = (const float*)d_in[4];
    const float* wk_b = (const float*)d_in[5];
    const float* wv_w = (const float*)d_in[6];
    const float* wv_b = (const float*)d_in[7];
    const float* wo_w = (const float*)d_in[8];
    const float* wo_b = (const float*)d_in[9];

    float* out  = (float*)d_out;
    float* attn = out + (size_t)NTv * Dv;   // outputs concatenated: out, then attn

    cudaFuncSetAttribute(attn_tc, cudaFuncAttributeMaxDynamicSharedMemorySize,
                         ATTN_SMEM);
    cudaFuncSetAttribute(tc_gemm<0>, cudaFuncAttributeMaxDynamicSharedMemorySize,
                         GEMM_SMEM);
    cudaFuncSetAttribute(tc_gemm<1>, cudaFuncAttributeMaxDynamicSharedMemorySize,
                         GEMM_SMEM);

    mask_flag_init<<<1, 1>>>();
    mask_flag_reduce<<<1024, 256>>>(mask, (Bv * Sv * Sv) / 4);

    tc_gemm<0><<<dim3(8, 32, 3), 256, GEMM_SMEM>>>(
        x, wq_w, wk_w, wv_w, wq_b, wk_b, wv_b, nullptr);
    attn_tc<<<dim3(Sv / 128, Hv, Bv), 256, ATTN_SMEM>>>(mask, attn);
    tc_gemm<1><<<dim3(8, 32, 1), 256, GEMM_SMEM>>>(
        nullptr, wo_w, nullptr, nullptr, wo_b, nullptr, nullptr, out);
}